// round 1
// baseline (speedup 1.0000x reference)
#include <cuda_runtime.h>

// ---------------------------------------------------------------------------
// Tree3: fused grouped-conv(5x5,g=3) + sigmoid + maxpool2 + tree-einsum +
// sigmoid + FC(336->10), one CTA per 4 images, everything staged in SMEM.
// ---------------------------------------------------------------------------

#define THREADS 512
#define TB 4                      // images per CTA
#define BTOT 2048

// shared-memory layout (float offsets)
#define IMG_ROW   33              // 32 cols + 1 pad
#define IMG_PLANE 1057            // 32*33 + 1 (plane stride == 1 mod 32 banks)
#define OFF_IMG   0
#define SZ_IMG    (TB*3*IMG_PLANE)        // 12684
#define POOL_CH   198                      // 14*14 + 2 pad (even -> float2 ok)
#define POOL_IMG  (45*POOL_CH)             // 8910
#define OFF_POOL  (OFF_IMG + SZ_IMG)
#define SZ_POOL   (TB*POOL_IMG)            // 35640
#define OFF_W     (OFF_POOL + SZ_POOL)     // conv weights 45*25
#define OFF_CB    (OFF_W + 1125)
#define OFF_T     (OFF_CB + 48)            // tree outputs TB*336
#define SMEM_FLOATS (OFF_T + TB*336)       // 50841 floats = 203,364 B

__device__ __forceinline__ float sigmoidf_fast(float v) {
    return 1.0f / (1.0f + __expf(-v));
}

__global__ __launch_bounds__(THREADS, 1)
void tree3_fused(const float* __restrict__ x,
                 const float* __restrict__ conv_w,
                 const float* __restrict__ conv_b,
                 const float* __restrict__ tree_w,
                 const float* __restrict__ tree_b,
                 const float* __restrict__ fc_w,
                 const float* __restrict__ fc_b,
                 float* __restrict__ out)
{
    extern __shared__ float sm[];
    float* s_img  = sm + OFF_IMG;
    float* s_pool = sm + OFF_POOL;
    float* s_w    = sm + OFF_W;
    float* s_cb   = sm + OFF_CB;
    float* s_t    = sm + OFF_T;

    const int tid = threadIdx.x;
    const int b0  = blockIdx.x * TB;

    // ---- stage conv weights + bias ----
    for (int idx = tid; idx < 1125; idx += THREADS) s_w[idx] = conv_w[idx];
    if (tid < 45) s_cb[tid] = conv_b[tid];

    // ---- stage 4 input images (padded layout) ----
    const float* xg = x + (size_t)b0 * 3072;
    for (int idx = tid; idx < TB * 3072; idx += THREADS) {
        int img = idx / 3072;
        int rem = idx - img * 3072;
        int g   = rem >> 10;          // 1024 per channel plane
        int rc  = rem & 1023;
        int row = rc >> 5;
        int col = rc & 31;
        s_img[(img * 3 + g) * IMG_PLANE + row * IMG_ROW + col] = xg[idx];
    }
    __syncthreads();

    // ---- phase 1: conv + bias + sigmoid(max) + pool into s_pool ----
    // task = (img, pi, half, c); c fastest so warp lanes hit <=3 image planes.
    for (int task = tid; task < TB * 45 * 28; task += THREADS) {
        int c    = task % 45;
        int rest = task / 45;         // [0, 112)
        int half = rest & 1;
        int pi   = (rest >> 1) % 14;
        int img  = rest / 28;

        int g  = c / 15;
        int y0 = pi * 2;
        int x0 = half * 14;
        const float* wb = s_w + c * 25;
        const float* ib = s_img + (img * 3 + g) * IMG_PLANE + y0 * IMG_ROW + x0;

        float acc0[14], acc1[14];
        #pragma unroll
        for (int k = 0; k < 14; k++) { acc0[k] = 0.f; acc1[k] = 0.f; }

        #pragma unroll
        for (int r = 0; r < 6; r++) {
            float in[18];
            const float* rp = ib + r * IMG_ROW;
            #pragma unroll
            for (int t = 0; t < 18; t++) in[t] = rp[t];
            if (r < 5) {
                #pragma unroll
                for (int kx = 0; kx < 5; kx++) {
                    float w = wb[r * 5 + kx];
                    #pragma unroll
                    for (int ox = 0; ox < 14; ox++)
                        acc0[ox] = fmaf(in[ox + kx], w, acc0[ox]);
                }
            }
            if (r > 0) {
                #pragma unroll
                for (int kx = 0; kx < 5; kx++) {
                    float w = wb[(r - 1) * 5 + kx];
                    #pragma unroll
                    for (int ox = 0; ox < 14; ox++)
                        acc1[ox] = fmaf(in[ox + kx], w, acc1[ox]);
                }
            }
        }

        float bias = s_cb[c];
        float* pb = s_pool + img * POOL_IMG + c * POOL_CH + pi * 14 + half * 7;
        #pragma unroll
        for (int pj = 0; pj < 7; pj++) {
            // sigmoid is monotone: pool-then-sigmoid == sigmoid-then-pool
            float v = fmaxf(fmaxf(acc0[2*pj], acc0[2*pj+1]),
                            fmaxf(acc1[2*pj], acc1[2*pj+1]));
            pb[pj] = sigmoidf_fast(v + bias);
        }
    }
    __syncthreads();

    // ---- phase 2: tree einsum + bias + sigmoid ----
    // t[b,f,g,i] = sum_{m,j,ki,kj} pool[g*15+m][2i+ki][2j+kj] * w[f,m,g,i,j,ki,kj]
    if (tid < 336) {
        int f   = tid / 21;
        int r21 = tid % 21;
        int g   = r21 / 7;
        int i   = r21 % 7;

        // float4 view: tree_w strides (in float4): f:2205, m:147, g:49, i:7, j:1
        const float4* wp = (const float4*)tree_w + (f * 2205 + g * 49 + i * 7);

        float acc[TB];
        #pragma unroll
        for (int t = 0; t < TB; t++) acc[t] = 0.f;

        const int chbase = g * 15;
        #pragma unroll 3
        for (int m = 0; m < 15; m++) {
            const float4* wm = wp + m * 147;
            int pbase = (chbase + m) * POOL_CH + (2 * i) * 14;
            #pragma unroll
            for (int j = 0; j < 7; j++) {
                float4 w = wm[j];
                #pragma unroll
                for (int img = 0; img < TB; img++) {
                    const float* pp = s_pool + img * POOL_IMG + pbase + 2 * j;
                    float2 r0 = *(const float2*)(pp);
                    float2 r1 = *(const float2*)(pp + 14);
                    acc[img] = fmaf(w.x, r0.x, acc[img]);
                    acc[img] = fmaf(w.y, r0.y, acc[img]);
                    acc[img] = fmaf(w.z, r1.x, acc[img]);
                    acc[img] = fmaf(w.w, r1.y, acc[img]);
                }
            }
        }

        float tb = tree_b[tid];     // tree_b index == f*21 + g*7 + i == tid
        #pragma unroll
        for (int img = 0; img < TB; img++)
            s_t[img * 336 + tid] = sigmoidf_fast(acc[img] + tb);
    }
    __syncthreads();

    // ---- phase 3: FC 336 -> 10 (8-way split + shuffle reduce) ----
    if (tid < 320) {
        int part  = tid & 7;
        int combo = tid >> 3;       // 0..39
        int img   = combo / 10;
        int o     = combo % 10;
        const float* tv = s_t + img * 336;
        const float* wv = fc_w + o * 336;
        float s = 0.f;
        for (int k = part; k < 336; k += 8)
            s = fmaf(tv[k], wv[k], s);
        s += __shfl_xor_sync(0xffffffffu, s, 1);
        s += __shfl_xor_sync(0xffffffffu, s, 2);
        s += __shfl_xor_sync(0xffffffffu, s, 4);
        if (part == 0)
            out[(b0 + img) * 10 + o] = s + fc_b[o];
    }
}

extern "C" void kernel_launch(void* const* d_in, const int* in_sizes, int n_in,
                              void* d_out, int out_size)
{
    const float* x      = (const float*)d_in[0];
    const float* conv_w = (const float*)d_in[1];
    const float* conv_b = (const float*)d_in[2];
    const float* tree_w = (const float*)d_in[3];
    const float* tree_b = (const float*)d_in[4];
    const float* fc_w   = (const float*)d_in[5];
    const float* fc_b   = (const float*)d_in[6];
    float* out = (float*)d_out;

    const int smem_bytes = SMEM_FLOATS * (int)sizeof(float);
    cudaFuncSetAttribute(tree3_fused,
                         cudaFuncAttributeMaxDynamicSharedMemorySize, smem_bytes);

    tree3_fused<<<BTOT / TB, THREADS, smem_bytes>>>(
        x, conv_w, conv_b, tree_w, tree_b, fc_w, fc_b, out);
}

// round 2
// speedup vs baseline: 1.0755x; 1.0755x over previous
#include <cuda_runtime.h>

// ---------------------------------------------------------------------------
// Tree3 fused, round 2: image-PAIR packed f32x2 datapath.
// Images are interleaved pairwise in SMEM (float2 = {imgA, imgB}), so every
// FMA is a packed fma.rn.f32x2 (2 fp32 FMAs / issue slot) and every shared
// load serves two images. One CTA = 4 images = 2 pairs.
// ---------------------------------------------------------------------------

#define THREADS 512
#define BTOT 2048
#define NPAIR 2                    // image pairs per CTA (4 images)

// float2-unit strides
#define IMG_ROW_F2   34            // 32 cols + 2 pad (even -> float4 aligned)
#define IMG_PLANE_F2 1088          // 32*34 (even -> every plane float4 aligned)
#define POOL_CH_F2   199           // 196 + 3 pad, odd -> conflict-free 8B banks

#define SZ_IMG_F2    (NPAIR*3*IMG_PLANE_F2)     // 6528
#define SZ_POOL_F2   (NPAIR*45*POOL_CH_F2)      // 17910
#define OFF_POOL_F2  SZ_IMG_F2
// float-unit offsets after the float2 regions
#define OFF_W        (2*(SZ_IMG_F2 + SZ_POOL_F2))   // 48876
#define OFF_CB       (OFF_W + 1128)
#define OFF_T        (OFF_CB + 48)
#define SMEM_FLOATS  (OFF_T + 4*336)                 // 51396 floats = 205,584 B

__device__ __forceinline__ float2 ffma2(float2 a, float2 b, float2 c) {
    unsigned long long au = *reinterpret_cast<unsigned long long*>(&a);
    unsigned long long bu = *reinterpret_cast<unsigned long long*>(&b);
    unsigned long long cu = *reinterpret_cast<unsigned long long*>(&c);
    unsigned long long du;
    asm("fma.rn.f32x2 %0, %1, %2, %3;" : "=l"(du) : "l"(au), "l"(bu), "l"(cu));
    return *reinterpret_cast<float2*>(&du);
}

__device__ __forceinline__ float sigmoidf_fast(float v) {
    return 1.0f / (1.0f + __expf(-v));
}

__global__ __launch_bounds__(THREADS, 1)
void tree3_fused(const float* __restrict__ x,
                 const float* __restrict__ conv_w,
                 const float* __restrict__ conv_b,
                 const float* __restrict__ tree_w,
                 const float* __restrict__ tree_b,
                 const float* __restrict__ fc_w,
                 const float* __restrict__ fc_b,
                 float* __restrict__ out)
{
    extern __shared__ __align__(16) float sm[];
    float2* s_img  = reinterpret_cast<float2*>(sm);               // [NPAIR*3][1088]
    float2* s_pool = reinterpret_cast<float2*>(sm) + OFF_POOL_F2; // [NPAIR*45][199]
    float*  s_w    = sm + OFF_W;
    float*  s_cb   = sm + OFF_CB;
    float*  s_t    = sm + OFF_T;

    const int tid = threadIdx.x;
    const int b0  = blockIdx.x * (2 * NPAIR);

    // ---- stage conv weights + bias ----
    for (int idx = tid; idx < 1125; idx += THREADS) s_w[idx] = conv_w[idx];
    if (tid < 45) s_cb[tid] = conv_b[tid];

    // ---- stage images, interleaved pairwise ----
    for (int idx = tid; idx < NPAIR * 3072; idx += THREADS) {
        int pair = idx / 3072;
        int rem  = idx - pair * 3072;
        int g    = rem >> 10;
        int rc   = rem & 1023;
        int row  = rc >> 5;
        int col  = rc & 31;
        const float* g0 = x + (size_t)(b0 + 2 * pair) * 3072 + g * 1024 + rc;
        s_img[(pair * 3 + g) * IMG_PLANE_F2 + row * IMG_ROW_F2 + col] =
            make_float2(g0[0], g0[3072]);
    }
    __syncthreads();

    // ---- phase 1: packed conv + sigmoid(max-pool) ----
    // task = (pair, pi, half, c); 2*14*2*45 = 2520 tasks.
    for (int task = tid; task < NPAIR * 45 * 28; task += THREADS) {
        int c    = task % 45;
        int rest = task / 45;          // [0,56)
        int half = rest & 1;
        int pi   = (rest >> 1) % 14;
        int pair = rest / 28;

        int g  = c / 15;
        int y0 = pi * 2;
        int x0 = half * 14;
        const float*  wb = s_w + c * 25;
        const float2* ib = s_img + (pair * 3 + g) * IMG_PLANE_F2
                                 + y0 * IMG_ROW_F2 + x0;

        float2 acc0[14], acc1[14];
        #pragma unroll
        for (int k = 0; k < 14; k++) {
            acc0[k] = make_float2(0.f, 0.f);
            acc1[k] = make_float2(0.f, 0.f);
        }

        float2 wpk[5];
        #pragma unroll
        for (int r = 0; r < 6; r++) {
            // load 18 packed columns as 9 float4 (short liveness)
            float2 P[18];
            const float4* rp = (const float4*)(ib + r * IMG_ROW_F2);
            #pragma unroll
            for (int u = 0; u < 9; u++) {
                float4 q = rp[u];
                P[2*u]   = make_float2(q.x, q.y);
                P[2*u+1] = make_float2(q.z, q.w);
            }
            if (r > 0) {                       // weights of row r-1 still in wpk
                #pragma unroll
                for (int kx = 0; kx < 5; kx++)
                    #pragma unroll
                    for (int ox = 0; ox < 14; ox++)
                        acc1[ox] = ffma2(P[ox + kx], wpk[kx], acc1[ox]);
            }
            if (r < 5) {
                #pragma unroll
                for (int kx = 0; kx < 5; kx++) {
                    float w = wb[r * 5 + kx];
                    wpk[kx] = make_float2(w, w);
                }
                #pragma unroll
                for (int kx = 0; kx < 5; kx++)
                    #pragma unroll
                    for (int ox = 0; ox < 14; ox++)
                        acc0[ox] = ffma2(P[ox + kx], wpk[kx], acc0[ox]);
            }
        }

        float bias = s_cb[c];
        float2* pb = s_pool + (pair * 45 + c) * POOL_CH_F2 + pi * 14 + half * 7;
        #pragma unroll
        for (int pj = 0; pj < 7; pj++) {
            // sigmoid monotone: pool-then-sigmoid == sigmoid-then-pool
            float vx = fmaxf(fmaxf(acc0[2*pj].x, acc0[2*pj+1].x),
                             fmaxf(acc1[2*pj].x, acc1[2*pj+1].x));
            float vy = fmaxf(fmaxf(acc0[2*pj].y, acc0[2*pj+1].y),
                             fmaxf(acc1[2*pj].y, acc1[2*pj+1].y));
            pb[pj] = make_float2(sigmoidf_fast(vx + bias),
                                 sigmoidf_fast(vy + bias));
        }
    }
    __syncthreads();

    // ---- phase 2: tree einsum (packed over image pairs) + sigmoid ----
    if (tid < 336) {
        int f   = tid / 21;
        int r21 = tid % 21;
        int g   = r21 / 7;
        int i   = r21 % 7;

        const float4* wp = (const float4*)tree_w + (f * 2205 + g * 49 + i * 7);

        float2 acc[NPAIR];
        #pragma unroll
        for (int p = 0; p < NPAIR; p++) acc[p] = make_float2(0.f, 0.f);

        #pragma unroll 3
        for (int m = 0; m < 15; m++) {
            const float4* wm = wp + m * 147;
            int ch = g * 15 + m;
            #pragma unroll
            for (int j = 0; j < 7; j++) {
                float4 w = wm[j];
                float2 wx = make_float2(w.x, w.x);
                float2 wy = make_float2(w.y, w.y);
                float2 wz = make_float2(w.z, w.z);
                float2 ww = make_float2(w.w, w.w);
                #pragma unroll
                for (int p = 0; p < NPAIR; p++) {
                    const float2* pp = s_pool + (p * 45 + ch) * POOL_CH_F2
                                              + (2 * i) * 14 + 2 * j;
                    acc[p] = ffma2(pp[0],  wx, acc[p]);
                    acc[p] = ffma2(pp[1],  wy, acc[p]);
                    acc[p] = ffma2(pp[14], wz, acc[p]);
                    acc[p] = ffma2(pp[15], ww, acc[p]);
                }
            }
        }

        float tb = tree_b[tid];
        #pragma unroll
        for (int p = 0; p < NPAIR; p++) {
            s_t[(2*p    ) * 336 + tid] = sigmoidf_fast(acc[p].x + tb);
            s_t[(2*p + 1) * 336 + tid] = sigmoidf_fast(acc[p].y + tb);
        }
    }
    __syncthreads();

    // ---- phase 3: FC 336 -> 10 ----
    if (tid < 320) {
        int part  = tid & 7;
        int combo = tid >> 3;        // 0..39
        int img   = combo / 10;
        int o     = combo % 10;
        const float* tv = s_t + img * 336;
        const float* wv = fc_w + o * 336;
        float s = 0.f;
        for (int k = part; k < 336; k += 8)
            s = fmaf(tv[k], wv[k], s);
        s += __shfl_xor_sync(0xffffffffu, s, 1);
        s += __shfl_xor_sync(0xffffffffu, s, 2);
        s += __shfl_xor_sync(0xffffffffu, s, 4);
        if (part == 0)
            out[(b0 + img) * 10 + o] = s + fc_b[o];
    }
}

extern "C" void kernel_launch(void* const* d_in, const int* in_sizes, int n_in,
                              void* d_out, int out_size)
{
    const float* x      = (const float*)d_in[0];
    const float* conv_w = (const float*)d_in[1];
    const float* conv_b = (const float*)d_in[2];
    const float* tree_w = (const float*)d_in[3];
    const float* tree_b = (const float*)d_in[4];
    const float* fc_w   = (const float*)d_in[5];
    const float* fc_b   = (const float*)d_in[6];
    float* out = (float*)d_out;

    const int smem_bytes = SMEM_FLOATS * (int)sizeof(float);
    cudaFuncSetAttribute(tree3_fused,
                         cudaFuncAttributeMaxDynamicSharedMemorySize, smem_bytes);

    tree3_fused<<<BTOT / (2 * NPAIR), THREADS, smem_bytes>>>(
        x, conv_w, conv_b, tree_w, tree_b, fc_w, fc_b, out);
}